// round 7
// baseline (speedup 1.0000x reference)
#include <cuda_runtime.h>
#include <cstdint>

#define NN 40000
#define EE 640000
#define DIM 128
#define NB 157   // ceil(40000/256)

// Scratch (static device globals — no allocation)
__device__ float g_hs[NN * DIM];   // h @ W (pre-scaled by dinv[row] on layers 1,2)
__device__ float g_h[NN * DIM];    // layer output
__device__ float g_dinv[NN];
__device__ int   g_cnt[NN];
__device__ int   g_off[NN];
__device__ int   g_pos[NN];
__device__ int   g_ssrc[EE];       // edge srcs sorted by dst (CSR)
__device__ int   g_bsum[NB];

// ---------------- degree / CSR build (5 launches) ----------------

__global__ void zero_k() {
    int i = blockIdx.x * blockDim.x + threadIdx.x;
    if (i < NN) g_cnt[i] = 0;
}

__global__ void count_k(const int* __restrict__ dst) {
    int e = blockIdx.x * blockDim.x + threadIdx.x;
    if (e < EE) atomicAdd(&g_cnt[dst[e]], 1);
}

// block sums + dinv fused
__global__ void scan1_k() {
    __shared__ int s[256];
    int i = blockIdx.x * 256 + threadIdx.x;
    int c = (i < NN) ? g_cnt[i] : 0;
    if (i < NN) g_dinv[i] = rsqrtf(1.0f + (float)c);
    s[threadIdx.x] = c;
    __syncthreads();
    for (int o = 128; o > 0; o >>= 1) {
        if (threadIdx.x < o) s[threadIdx.x] += s[threadIdx.x + o];
        __syncthreads();
    }
    if (threadIdx.x == 0) g_bsum[blockIdx.x] = s[0];
}

// per-block base reduced inline + intra-block scan
__global__ void scan3_k() {
    __shared__ int s[256];
    __shared__ int bb[256];
    int t = threadIdx.x;
    int i = blockIdx.x * 256 + t;

    int b = (t < blockIdx.x) ? g_bsum[t] : 0;
    bb[t] = b;
    int v = (i < NN) ? g_cnt[i] : 0;
    s[t] = v;
    __syncthreads();
    for (int o = 128; o > 0; o >>= 1) {
        if (t < o) bb[t] += bb[t + o];
        __syncthreads();
    }
    for (int o = 1; o < 256; o <<= 1) {
        int add = (t >= o) ? s[t - o] : 0;
        __syncthreads();
        s[t] += add;
        __syncthreads();
    }
    if (i < NN) {
        int off = bb[0] + s[t] - v;
        g_off[i] = off;
        g_pos[i] = off;
    }
}

__global__ void place_k(const int* __restrict__ src, const int* __restrict__ dst) {
    int e = blockIdx.x * blockDim.x + threadIdx.x;
    if (e < EE) {
        int d = dst[e];
        int p = atomicAdd(&g_pos[d], 1);
        g_ssrc[p] = src[e];
    }
}

// ---------------- tf32 tensor-core GEMM: g_hs = (A @ W) [* dinv[row] if SCALE] ----------------
// W staged in smem (tf32, stride 132 -> conflict-free); A fragments loaded
// directly from gmem (rows L1-resident across the 16 k-steps), cvt in regs.

__device__ __forceinline__ uint32_t f2tf32(float f) {
    uint32_t r;
    asm("cvt.rna.tf32.f32 %0, %1;" : "=r"(r) : "f"(f));
    return r;
}

#define SM_STRIDE 132
#define GEMM_SMEM (128 * SM_STRIDE * 4)

template <bool FROM_H, bool SCALE>
__global__ void gemm_tc(const float* __restrict__ Ax, const float* __restrict__ W) {
    const float* __restrict__ A = FROM_H ? (const float*)g_h : Ax;
    extern __shared__ uint32_t sW[];      // [128][132]

    int tid = threadIdx.x;
    int r0 = blockIdx.x * 128;

    #pragma unroll
    for (int i = tid; i < 128 * 32; i += 256) {
        int k = i >> 5, c4 = (i & 31) << 2;
        float4 v = *(const float4*)&W[k * DIM + c4];
        uint32_t* p = &sW[k * SM_STRIDE + c4];
        p[0] = f2tf32(v.x); p[1] = f2tf32(v.y); p[2] = f2tf32(v.z); p[3] = f2tf32(v.w);
    }
    __syncthreads();

    int warp = tid >> 5, lane = tid & 31;
    int g = lane >> 2, tg = lane & 3;
    int rbase = warp * 16;

    int row0 = r0 + rbase + g;
    int row1 = row0 + 8;
    const float* arow0 = &A[min(row0, NN - 1) * DIM];
    const float* arow1 = &A[min(row1, NN - 1) * DIM];

    float c[16][4];
    #pragma unroll
    for (int nt = 0; nt < 16; nt++) {
        c[nt][0] = 0.f; c[nt][1] = 0.f; c[nt][2] = 0.f; c[nt][3] = 0.f;
    }

    #pragma unroll
    for (int kt = 0; kt < 16; kt++) {
        int k0 = kt * 8;
        uint32_t a0 = f2tf32(arow0[k0 + tg]);
        uint32_t a1 = f2tf32(arow1[k0 + tg]);
        uint32_t a2 = f2tf32(arow0[k0 + tg + 4]);
        uint32_t a3 = f2tf32(arow1[k0 + tg + 4]);
        #pragma unroll
        for (int nt = 0; nt < 16; nt++) {
            uint32_t b0 = sW[(k0 + tg) * SM_STRIDE + nt * 8 + g];
            uint32_t b1 = sW[(k0 + tg + 4) * SM_STRIDE + nt * 8 + g];
            asm volatile(
                "mma.sync.aligned.m16n8k8.row.col.f32.tf32.tf32.f32 "
                "{%0,%1,%2,%3}, {%4,%5,%6,%7}, {%8,%9}, {%0,%1,%2,%3};\n"
                : "+f"(c[nt][0]), "+f"(c[nt][1]), "+f"(c[nt][2]), "+f"(c[nt][3])
                : "r"(a0), "r"(a1), "r"(a2), "r"(a3), "r"(b0), "r"(b1));
        }
    }

    float d0 = 1.f, d1 = 1.f;
    if (SCALE) {   // layer 0 must NOT touch g_dinv (CSR chain runs concurrently)
        d0 = (row0 < NN) ? g_dinv[row0] : 0.f;
        d1 = (row1 < NN) ? g_dinv[row1] : 0.f;
    }
    #pragma unroll
    for (int nt = 0; nt < 16; nt++) {
        int col = nt * 8 + 2 * tg;
        if (row0 < NN) {
            float2 o; o.x = c[nt][0] * d0; o.y = c[nt][1] * d0;
            *(float2*)&g_hs[row0 * DIM + col] = o;
        }
        if (row1 < NN) {
            float2 o; o.x = c[nt][2] * d1; o.y = c[nt][3] * d1;
            *(float2*)&g_hs[row1 * DIM + col] = o;
        }
    }
}

// ---------------- Aggregation: one warp per node, index prefetch + shfl ----------------
// Indices for up to 32 edges loaded coalesced by lanes, broadcast via shfl;
// row gathers are then fully independent (high MLP).
// SCALE_SRC (layer 0): dinv[s] prefetched per-lane, shfl'd with the index.

template <bool SCALE_SRC, bool FINAL>
__global__ void agg_k(const float* __restrict__ bias,
                      const float* __restrict__ lw,
                      const float* __restrict__ lb,
                      float* __restrict__ out) {
    int w = (blockIdx.x * blockDim.x + threadIdx.x) >> 5;
    int lane = threadIdx.x & 31;
    if (w >= NN) return;
    int l4 = lane * 4;
    const float* hs_l = &g_hs[l4];

    const int* ss = &g_ssrc[g_off[w]];
    int n = g_cnt[w];
    float4 acc = make_float4(0.f, 0.f, 0.f, 0.f);

    for (int base = 0; base < n; base += 32) {
        int cnt = min(32, n - base);
        int idx = (lane < cnt) ? ss[base + lane] : 0;
        float dv = 1.f;
        if (SCALE_SRC) dv = (lane < cnt) ? g_dinv[idx] : 1.f;

        #pragma unroll 4
        for (int j = 0; j < cnt; j++) {
            int s = __shfl_sync(0xffffffffu, idx, j);
            float4 v = *(const float4*)&hs_l[s * DIM];
            float sc = SCALE_SRC ? __shfl_sync(0xffffffffu, dv, j) : 1.f;
            acc.x = fmaf(v.x, sc, acc.x);
            acc.y = fmaf(v.y, sc, acc.y);
            acc.z = fmaf(v.z, sc, acc.z);
            acc.w = fmaf(v.w, sc, acc.w);
        }
    }

    float di = g_dinv[w];
    float4 self = *(const float4*)&hs_l[w * DIM];
    float selfsc = SCALE_SRC ? di : 1.f;
    float4 bb = *(const float4*)&bias[l4];

    float4 r;
    r.x = fmaxf(di * (acc.x + self.x * selfsc) + bb.x, 0.f);
    r.y = fmaxf(di * (acc.y + self.y * selfsc) + bb.y, 0.f);
    r.z = fmaxf(di * (acc.z + self.z * selfsc) + bb.z, 0.f);
    r.w = fmaxf(di * (acc.w + self.w * selfsc) + bb.w, 0.f);

    if (FINAL) {
        float4 lwv = *(const float4*)&lw[l4];
        float p = r.x * lwv.x + r.y * lwv.y + r.z * lwv.z + r.w * lwv.w;
        #pragma unroll
        for (int o = 16; o > 0; o >>= 1) p += __shfl_xor_sync(0xffffffffu, p, o);
        if (lane == 0) out[w] = p + lb[0];
    } else {
        *(float4*)&g_h[w * DIM + l4] = r;
    }
}

// ---------------- launch ----------------

extern "C" void kernel_launch(void* const* d_in, const int* in_sizes, int n_in,
                              void* d_out, int out_size) {
    const float* x  = (const float*)d_in[0];
    const int*   ei = (const int*)d_in[1];
    const int*   src = ei;
    const int*   dst = ei + EE;
    const float* W0 = (const float*)d_in[2];
    const float* b0 = (const float*)d_in[3];
    const float* W1 = (const float*)d_in[4];
    const float* b1 = (const float*)d_in[5];
    const float* W2 = (const float*)d_in[6];
    const float* b2 = (const float*)d_in[7];
    const float* lw = (const float*)d_in[8];
    const float* lb = (const float*)d_in[9];
    float* out = (float*)d_out;

    static cudaStream_t s2 = nullptr;
    static cudaEvent_t evFork = nullptr, evJoin = nullptr;
    if (s2 == nullptr) {
        cudaStreamCreateWithFlags(&s2, cudaStreamNonBlocking);
        cudaEventCreateWithFlags(&evFork, cudaEventDisableTiming);
        cudaEventCreateWithFlags(&evJoin, cudaEventDisableTiming);
        cudaFuncSetAttribute(gemm_tc<false, false>, cudaFuncAttributeMaxDynamicSharedMemorySize, GEMM_SMEM);
        cudaFuncSetAttribute(gemm_tc<true, true>,   cudaFuncAttributeMaxDynamicSharedMemorySize, GEMM_SMEM);
    }

    const int GEMM_BLOCKS = (NN + 127) / 128;   // 313
    const int AGG_BLOCKS = (NN * 32) / 256;     // one warp per node

    // Fork: CSR build on s2, concurrent with layer-0 GEMM (which needs no dinv).
    cudaEventRecord(evFork, 0);
    cudaStreamWaitEvent(s2, evFork, 0);
    zero_k<<<NB, 256, 0, s2>>>();
    count_k<<<EE / 256, 256, 0, s2>>>(dst);
    scan1_k<<<NB, 256, 0, s2>>>();
    scan3_k<<<NB, 256, 0, s2>>>();
    place_k<<<EE / 256, 256, 0, s2>>>(src, dst);
    cudaEventRecord(evJoin, s2);

    gemm_tc<false, false><<<GEMM_BLOCKS, 256, GEMM_SMEM>>>(x, W0);   // hs0 = x @ W0 (unscaled)
    cudaStreamWaitEvent(0, evJoin, 0);                               // join before agg0

    // layer 0 (src-side dinv applied per edge via prefetched lanes)
    agg_k<true, false><<<AGG_BLOCKS, 256>>>(b0, nullptr, nullptr, nullptr);
    // layer 1
    gemm_tc<true, true><<<GEMM_BLOCKS, 256, GEMM_SMEM>>>(nullptr, W1);
    agg_k<false, false><<<AGG_BLOCKS, 256>>>(b1, nullptr, nullptr, nullptr);
    // layer 2 + final linear fused
    gemm_tc<true, true><<<GEMM_BLOCKS, 256, GEMM_SMEM>>>(nullptr, W2);
    agg_k<false, true><<<AGG_BLOCKS, 256>>>(b2, lw, lb, out);
}

// round 8
// speedup vs baseline: 1.1022x; 1.1022x over previous
#include <cuda_runtime.h>
#include <cuda_fp16.h>
#include <cstdint>

#define NN 40000
#define EE 640000
#define DIM 128
#define NB 157   // ceil(40000/256)

// Scratch (static device globals — no allocation)
__device__ __half g_hs[NN * DIM];  // h @ W (fp16; pre-scaled by dinv[row] on layers 1,2)
__device__ float  g_h[NN * DIM];   // layer output (fp32)
__device__ float  g_dinv[NN];
__device__ int    g_cnt[NN];
__device__ int    g_off[NN];
__device__ int    g_pos[NN];
__device__ int    g_ssrc[EE];      // edge srcs sorted by dst (CSR)
__device__ int    g_bsum[NB];

// ---------------- degree / CSR build (5 launches) ----------------

__global__ void zero_k() {
    int i = blockIdx.x * blockDim.x + threadIdx.x;
    if (i < NN) g_cnt[i] = 0;
}

__global__ void count_k(const int* __restrict__ dst) {
    int e = blockIdx.x * blockDim.x + threadIdx.x;
    if (e < EE) atomicAdd(&g_cnt[dst[e]], 1);
}

// block sums + dinv fused
__global__ void scan1_k() {
    __shared__ int s[256];
    int i = blockIdx.x * 256 + threadIdx.x;
    int c = (i < NN) ? g_cnt[i] : 0;
    if (i < NN) g_dinv[i] = rsqrtf(1.0f + (float)c);
    s[threadIdx.x] = c;
    __syncthreads();
    for (int o = 128; o > 0; o >>= 1) {
        if (threadIdx.x < o) s[threadIdx.x] += s[threadIdx.x + o];
        __syncthreads();
    }
    if (threadIdx.x == 0) g_bsum[blockIdx.x] = s[0];
}

// per-block base reduced inline + intra-block scan
__global__ void scan3_k() {
    __shared__ int s[256];
    __shared__ int bb[256];
    int t = threadIdx.x;
    int i = blockIdx.x * 256 + t;

    int b = (t < blockIdx.x) ? g_bsum[t] : 0;
    bb[t] = b;
    int v = (i < NN) ? g_cnt[i] : 0;
    s[t] = v;
    __syncthreads();
    for (int o = 128; o > 0; o >>= 1) {
        if (t < o) bb[t] += bb[t + o];
        __syncthreads();
    }
    for (int o = 1; o < 256; o <<= 1) {
        int add = (t >= o) ? s[t - o] : 0;
        __syncthreads();
        s[t] += add;
        __syncthreads();
    }
    if (i < NN) {
        int off = bb[0] + s[t] - v;
        g_off[i] = off;
        g_pos[i] = off;
    }
}

__global__ void place_k(const int* __restrict__ src, const int* __restrict__ dst) {
    int e = blockIdx.x * blockDim.x + threadIdx.x;
    if (e < EE) {
        int d = dst[e];
        int p = atomicAdd(&g_pos[d], 1);
        g_ssrc[p] = src[e];
    }
}

// ---------------- tf32 tensor-core GEMM: g_hs(fp16) = (A @ W) [* dinv[row] if SCALE] ----------------
// W staged in smem (tf32, stride 132 -> conflict-free); A fragments loaded
// directly from gmem (rows L1-resident across the 16 k-steps), cvt in regs.

__device__ __forceinline__ uint32_t f2tf32(float f) {
    uint32_t r;
    asm("cvt.rna.tf32.f32 %0, %1;" : "=r"(r) : "f"(f));
    return r;
}

#define SM_STRIDE 132
#define GEMM_SMEM (128 * SM_STRIDE * 4)

template <bool FROM_H, bool SCALE>
__global__ void gemm_tc(const float* __restrict__ Ax, const float* __restrict__ W) {
    const float* __restrict__ A = FROM_H ? (const float*)g_h : Ax;
    extern __shared__ uint32_t sW[];      // [128][132]

    int tid = threadIdx.x;
    int r0 = blockIdx.x * 128;

    #pragma unroll
    for (int i = tid; i < 128 * 32; i += 256) {
        int k = i >> 5, c4 = (i & 31) << 2;
        float4 v = *(const float4*)&W[k * DIM + c4];
        uint32_t* p = &sW[k * SM_STRIDE + c4];
        p[0] = f2tf32(v.x); p[1] = f2tf32(v.y); p[2] = f2tf32(v.z); p[3] = f2tf32(v.w);
    }
    __syncthreads();

    int warp = tid >> 5, lane = tid & 31;
    int g = lane >> 2, tg = lane & 3;
    int rbase = warp * 16;

    int row0 = r0 + rbase + g;
    int row1 = row0 + 8;
    const float* arow0 = &A[min(row0, NN - 1) * DIM];
    const float* arow1 = &A[min(row1, NN - 1) * DIM];

    float c[16][4];
    #pragma unroll
    for (int nt = 0; nt < 16; nt++) {
        c[nt][0] = 0.f; c[nt][1] = 0.f; c[nt][2] = 0.f; c[nt][3] = 0.f;
    }

    #pragma unroll
    for (int kt = 0; kt < 16; kt++) {
        int k0 = kt * 8;
        uint32_t a0 = f2tf32(arow0[k0 + tg]);
        uint32_t a1 = f2tf32(arow1[k0 + tg]);
        uint32_t a2 = f2tf32(arow0[k0 + tg + 4]);
        uint32_t a3 = f2tf32(arow1[k0 + tg + 4]);
        #pragma unroll
        for (int nt = 0; nt < 16; nt++) {
            uint32_t b0 = sW[(k0 + tg) * SM_STRIDE + nt * 8 + g];
            uint32_t b1 = sW[(k0 + tg + 4) * SM_STRIDE + nt * 8 + g];
            asm volatile(
                "mma.sync.aligned.m16n8k8.row.col.f32.tf32.tf32.f32 "
                "{%0,%1,%2,%3}, {%4,%5,%6,%7}, {%8,%9}, {%0,%1,%2,%3};\n"
                : "+f"(c[nt][0]), "+f"(c[nt][1]), "+f"(c[nt][2]), "+f"(c[nt][3])
                : "r"(a0), "r"(a1), "r"(a2), "r"(a3), "r"(b0), "r"(b1));
        }
    }

    float d0 = 1.f, d1 = 1.f;
    if (SCALE) {   // layer 0 must NOT touch g_dinv (CSR chain runs concurrently)
        d0 = (row0 < NN) ? g_dinv[row0] : 0.f;
        d1 = (row1 < NN) ? g_dinv[row1] : 0.f;
    }
    #pragma unroll
    for (int nt = 0; nt < 16; nt++) {
        int col = nt * 8 + 2 * tg;
        if (row0 < NN) {
            __half2 o = __floats2half2_rn(c[nt][0] * d0, c[nt][1] * d0);
            *(__half2*)&g_hs[row0 * DIM + col] = o;
        }
        if (row1 < NN) {
            __half2 o = __floats2half2_rn(c[nt][2] * d1, c[nt][3] * d1);
            *(__half2*)&g_hs[row1 * DIM + col] = o;
        }
    }
}

// ---------------- Aggregation: one warp per node, fp16 gather, fp32 accum ----------------
// Indices for up to 32 edges loaded coalesced by lanes, broadcast via shfl.
// Each lane gathers 4 halves (uint2 = 8B) per edge -> 256B/row, fully coalesced.
// SCALE_SRC (layer 0): dinv[s] prefetched per-lane, shfl'd with the index.

template <bool SCALE_SRC, bool FINAL>
__global__ void agg_k(const float* __restrict__ bias,
                      const float* __restrict__ lw,
                      const float* __restrict__ lb,
                      float* __restrict__ out) {
    int w = (blockIdx.x * blockDim.x + threadIdx.x) >> 5;
    int lane = threadIdx.x & 31;
    if (w >= NN) return;
    int l4 = lane * 4;
    const __half* hs_l = &g_hs[l4];

    const int* ss = &g_ssrc[g_off[w]];
    int n = g_cnt[w];
    float4 acc = make_float4(0.f, 0.f, 0.f, 0.f);

    for (int base = 0; base < n; base += 32) {
        int cnt = min(32, n - base);
        int idx = (lane < cnt) ? ss[base + lane] : 0;
        float dv = 1.f;
        if (SCALE_SRC) dv = (lane < cnt) ? g_dinv[idx] : 1.f;

        #pragma unroll 4
        for (int j = 0; j < cnt; j++) {
            int s = __shfl_sync(0xffffffffu, idx, j);
            uint2 rv = *(const uint2*)&hs_l[s * DIM];
            float2 f0 = __half22float2(*(__half2*)&rv.x);
            float2 f1 = __half22float2(*(__half2*)&rv.y);
            float sc = SCALE_SRC ? __shfl_sync(0xffffffffu, dv, j) : 1.f;
            acc.x = fmaf(f0.x, sc, acc.x);
            acc.y = fmaf(f0.y, sc, acc.y);
            acc.z = fmaf(f1.x, sc, acc.z);
            acc.w = fmaf(f1.y, sc, acc.w);
        }
    }

    float di = g_dinv[w];
    uint2 sv = *(const uint2*)&hs_l[w * DIM];
    float2 s0 = __half22float2(*(__half2*)&sv.x);
    float2 s1 = __half22float2(*(__half2*)&sv.y);
    float selfsc = SCALE_SRC ? di : 1.f;
    float4 bb = *(const float4*)&bias[l4];

    float4 r;
    r.x = fmaxf(di * (acc.x + s0.x * selfsc) + bb.x, 0.f);
    r.y = fmaxf(di * (acc.y + s0.y * selfsc) + bb.y, 0.f);
    r.z = fmaxf(di * (acc.z + s1.x * selfsc) + bb.z, 0.f);
    r.w = fmaxf(di * (acc.w + s1.y * selfsc) + bb.w, 0.f);

    if (FINAL) {
        float4 lwv = *(const float4*)&lw[l4];
        float p = r.x * lwv.x + r.y * lwv.y + r.z * lwv.z + r.w * lwv.w;
        #pragma unroll
        for (int o = 16; o > 0; o >>= 1) p += __shfl_xor_sync(0xffffffffu, p, o);
        if (lane == 0) out[w] = p + lb[0];
    } else {
        *(float4*)&g_h[w * DIM + l4] = r;
    }
}

// ---------------- launch ----------------

extern "C" void kernel_launch(void* const* d_in, const int* in_sizes, int n_in,
                              void* d_out, int out_size) {
    const float* x  = (const float*)d_in[0];
    const int*   ei = (const int*)d_in[1];
    const int*   src = ei;
    const int*   dst = ei + EE;
    const float* W0 = (const float*)d_in[2];
    const float* b0 = (const float*)d_in[3];
    const float* W1 = (const float*)d_in[4];
    const float* b1 = (const float*)d_in[5];
    const float* W2 = (const float*)d_in[6];
    const float* b2 = (const float*)d_in[7];
    const float* lw = (const float*)d_in[8];
    const float* lb = (const float*)d_in[9];
    float* out = (float*)d_out;

    static cudaStream_t s2 = nullptr;
    static cudaEvent_t evFork = nullptr, evJoin = nullptr;
    if (s2 == nullptr) {
        cudaStreamCreateWithFlags(&s2, cudaStreamNonBlocking);
        cudaEventCreateWithFlags(&evFork, cudaEventDisableTiming);
        cudaEventCreateWithFlags(&evJoin, cudaEventDisableTiming);
        cudaFuncSetAttribute(gemm_tc<false, false>, cudaFuncAttributeMaxDynamicSharedMemorySize, GEMM_SMEM);
        cudaFuncSetAttribute(gemm_tc<true, true>,   cudaFuncAttributeMaxDynamicSharedMemorySize, GEMM_SMEM);
    }

    const int GEMM_BLOCKS = (NN + 127) / 128;   // 313
    const int AGG_BLOCKS = (NN * 32) / 256;     // one warp per node

    // Fork: CSR build on s2, concurrent with layer-0 GEMM (which needs no dinv).
    cudaEventRecord(evFork, 0);
    cudaStreamWaitEvent(s2, evFork, 0);
    zero_k<<<NB, 256, 0, s2>>>();
    count_k<<<EE / 256, 256, 0, s2>>>(dst);
    scan1_k<<<NB, 256, 0, s2>>>();
    scan3_k<<<NB, 256, 0, s2>>>();
    place_k<<<EE / 256, 256, 0, s2>>>(src, dst);
    cudaEventRecord(evJoin, s2);

    gemm_tc<false, false><<<GEMM_BLOCKS, 256, GEMM_SMEM>>>(x, W0);   // hs0 = x @ W0 (unscaled)
    cudaStreamWaitEvent(0, evJoin, 0);                               // join before agg0

    // layer 0 (src-side dinv applied per edge via prefetched lanes)
    agg_k<true, false><<<AGG_BLOCKS, 256>>>(b0, nullptr, nullptr, nullptr);
    // layer 1
    gemm_tc<true, true><<<GEMM_BLOCKS, 256, GEMM_SMEM>>>(nullptr, W1);
    agg_k<false, false><<<AGG_BLOCKS, 256>>>(b1, nullptr, nullptr, nullptr);
    // layer 2 + final linear fused
    gemm_tc<true, true><<<GEMM_BLOCKS, 256, GEMM_SMEM>>>(nullptr, W2);
    agg_k<false, true><<<AGG_BLOCKS, 256>>>(b2, lw, lb, out);
}